// round 6
// baseline (speedup 1.0000x reference)
#include <cuda_runtime.h>
#include <cuda_bf16.h>
#include <math.h>

#define NN   4096
#define FF   512
#define HH   60
#define CC   4
#define CAP  64      // max nnz per row of sub_adj (mean ~8.2)

// scratch (device globals; referenced ONLY from device code — see R3 post-mortem)
__device__ float g_deg[NN];          // zero at load; reset to 0 by k_xw each run
__device__ float g_dis[NN];
__device__ float g_self[NN];         // dis_i^2 (self-loop weight)
__device__ int   g_cnt[NN];
__device__ int   g_cols[NN * CAP];
__device__ float g_vals[NN * CAP];   // after k_norm: fully normalized edge weight
__device__ float g_Ta[NN * HH];
__device__ float g_Tb[NN * HH];

__device__ __forceinline__ void cp16(unsigned s, const void* g) {
    asm volatile("cp.async.cg.shared.global [%0], [%1], 16;\n" :: "r"(s), "l"(g));
}

// ---------------------------------------------------------------------------
// K1: scan sub_adj (67 MB, HBM floor), build per-row edge lists (warp-ballot
// compaction), gather P_vec at nonzeros, sigmoid, column-degree accumulation.
__global__ void k_build(const float* __restrict__ adj, const float* __restrict__ pvec) {
    int warp = (blockIdx.x * blockDim.x + threadIdx.x) >> 5;
    int lane = threadIdx.x & 31;
    if (warp >= NN) return;
    const int row = warp;
    const float4* rp = reinterpret_cast<const float4*>(adj + (size_t)row * NN);
    int cnt = 0;
    #pragma unroll 4
    for (int it = 0; it < NN / 128; ++it) {
        float4 v = rp[it * 32 + lane];
        int jb = it * 128 + lane * 4;
        float vv[4] = {v.x, v.y, v.z, v.w};
        #pragma unroll
        for (int q = 0; q < 4; ++q) {
            bool nz = (vv[q] != 0.0f);
            unsigned m = __ballot_sync(0xffffffffu, nz);
            if (nz) {
                int j = jb + q;
                int slot = cnt + __popc(m & ((1u << lane) - 1u));
                int a = row > j ? row : j;
                int b = row > j ? j : row;
                float p = pvec[(size_t)a * (a + 1) / 2 + b];   // tril index a(a+1)/2+b
                float s = vv[q] / (1.0f + expf(-p));            // sigmoid(p)*adj
                if (slot < CAP) {
                    g_cols[row * CAP + slot] = j;
                    g_vals[row * CAP + slot] = s;
                }
                atomicAdd(&g_deg[j], s);                        // column sum
            }
            cnt += __popc(m);
        }
    }
    if (lane == 0) g_cnt[row] = cnt < CAP ? cnt : CAP;
}

// ---------------------------------------------------------------------------
// K2: g_Ta = x @ W1 (4096x512 @ 512x60). 128 blocks x 512 threads, BM=32,
// cp.async double-buffered, packed f32x2. Prologue finalizes g_dis, resets g_deg.
__global__ void __launch_bounds__(512) k_xw(const float* __restrict__ x,
                                            const float* __restrict__ W) {
    int gid = blockIdx.x * 512 + threadIdx.x;
    if (gid < NN) {
        g_dis[gid] = rsqrtf(g_deg[gid] + 1.0f);  // +1: identity self-loop
        g_deg[gid] = 0.0f;                       // reset for graph replay
    }

    __shared__ __align__(16) float As[2][32][36];  // [buf][row][k]
    __shared__ __align__(16) float Ws[2][32][64];  // [buf][k][col], 60..63 zero

    const int t  = threadIdx.x;
    const int tx = t & 15;            // 4 cols each
    const int ty = t >> 4;            // 1 row each (0..31)
    const int r0 = blockIdx.x * 32;

    if (t < 256) {  // zero pad cols 60..63: 2 bufs x 32 k x 4
        int b = t >> 7, rr = (t >> 2) & 31, cc = 60 + (t & 3);
        Ws[b][rr][cc] = 0.0f;
    }

    auto issue = [&](int tile, int buf) {
        int k0 = tile * 32;
        if (t < 256) {                          // A: 32x32 floats, 16B each
            int arow = t >> 3, akk = (t & 7) * 4;
            unsigned sA = (unsigned)__cvta_generic_to_shared(&As[buf][arow][akk]);
            cp16(sA, x + (size_t)(r0 + arow) * FF + k0 + akk);
        } else {                                // W: 32x60 floats
            int u = t - 256;
            int wk = u >> 3, wc = (u & 7) * 8;
            unsigned sW = (unsigned)__cvta_generic_to_shared(&Ws[buf][wk][wc]);
            cp16(sW, W + (size_t)(k0 + wk) * HH + wc);
            if (wc + 4 < HH)
                cp16(sW + 16, W + (size_t)(k0 + wk) * HH + wc + 4);
        }
        asm volatile("cp.async.commit_group;\n");
    };

    unsigned long long acc0 = 0ull, acc1 = 0ull;   // 4 cols packed f32x2

    issue(0, 0);
    int buf = 0;
    for (int tile = 0; tile < FF / 32; ++tile) {
        __syncthreads();
        if (tile < FF / 32 - 1) {
            issue(tile + 1, buf ^ 1);
            asm volatile("cp.async.wait_group 1;\n");
        } else {
            asm volatile("cp.async.wait_group 0;\n");
        }
        __syncthreads();
        #pragma unroll
        for (int k = 0; k < 32; ++k) {
            unsigned a = __float_as_uint(As[buf][ty][k]);
            unsigned long long pa;
            asm("mov.b64 %0, {%1, %1};" : "=l"(pa) : "r"(a));
            ulonglong2 w = *reinterpret_cast<const ulonglong2*>(&Ws[buf][k][4 * tx]);
            asm("fma.rn.f32x2 %0, %1, %2, %0;" : "+l"(acc0) : "l"(pa), "l"(w.x));
            asm("fma.rn.f32x2 %0, %1, %2, %0;" : "+l"(acc1) : "l"(pa), "l"(w.y));
        }
        buf ^= 1;
    }

    if (4 * tx < HH) {
        unsigned lo0, hi0, lo1, hi1;
        asm("mov.b64 {%0, %1}, %2;" : "=r"(lo0), "=r"(hi0) : "l"(acc0));
        asm("mov.b64 {%0, %1}, %2;" : "=r"(lo1), "=r"(hi1) : "l"(acc1));
        float4 o = make_float4(__uint_as_float(lo0), __uint_as_float(hi0),
                               __uint_as_float(lo1), __uint_as_float(hi1));
        *reinterpret_cast<float4*>(&g_Ta[(size_t)(r0 + ty) * HH + 4 * tx]) = o;
    }
}

// ---------------------------------------------------------------------------
// K3: normalize edge weights in place: g_vals *= dis_i*dis_j; g_self = dis_i^2.
// 16 threads per row, 1 edge/thread (cnt ~9 < 16 nearly always).
__global__ void k_norm() {
    int gid = blockIdx.x * 256 + threadIdx.x;
    int row = gid >> 4, le = gid & 15;
    if (row >= NN) return;
    float di = g_dis[row];
    int cnt = g_cnt[row];
    for (int e = le; e < cnt; e += 16)
        g_vals[row * CAP + e] *= di * g_dis[g_cols[row * CAP + e]];
    if (le == 0) g_self[row] = di * di;
}

// ---------------------------------------------------------------------------
// K4: fused  H = relu(SpMM(norm_adj, Tin) + bias);  Tout = H @ Wnext
// 512 threads = 8 groups x 64 lanes; 8 rows/block; MLP-4 gathers; Wnext in smem.
__global__ void __launch_bounds__(512) k_layer(int src, const float* __restrict__ bias,
                                               const float* __restrict__ Wnext) {
    const float* __restrict__ Tin = src ? g_Tb : g_Ta;
    float* __restrict__ Tout      = src ? g_Ta : g_Tb;
    __shared__ float Ws[HH * HH];
    __shared__ float hs[8][HH];
    int t = threadIdx.x, c = t & 63, g = t >> 6;
    int row = blockIdx.x * 8 + g;
    for (int i = t; i < HH * HH; i += 512) Ws[i] = Wnext[i];
    if (c < HH) {
        const int*   cp = &g_cols[row * CAP];
        const float* vp = &g_vals[row * CAP];
        int cnt = g_cnt[row];
        float a0 = g_self[row] * Tin[row * HH + c], a1 = 0.f, a2 = 0.f, a3 = 0.f;
        int e = 0;
        for (; e + 4 <= cnt; e += 4) {
            int   c0 = cp[e], c1 = cp[e + 1], c2 = cp[e + 2], c3 = cp[e + 3];
            float w0 = vp[e], w1 = vp[e + 1], w2 = vp[e + 2], w3 = vp[e + 3];
            a0 += w0 * Tin[c0 * HH + c];
            a1 += w1 * Tin[c1 * HH + c];
            a2 += w2 * Tin[c2 * HH + c];
            a3 += w3 * Tin[c3 * HH + c];
        }
        for (; e < cnt; ++e) a0 += vp[e] * Tin[cp[e] * HH + c];
        hs[g][c] = fmaxf(((a0 + a1) + (a2 + a3)) + bias[c], 0.0f);
    }
    __syncthreads();
    if (c < HH) {
        float o = 0.0f;
        #pragma unroll
        for (int k = 0; k < HH; ++k)
            o += hs[g][k] * Ws[k * HH + c];
        Tout[row * HH + c] = o;
    }
}

// ---------------------------------------------------------------------------
// K5: H3 = SpMM(g_Ta) + b3; logits = H3 @ lin_w + lin_b; out = log_softmax.
__global__ void __launch_bounds__(512) k_final(const float* __restrict__ b3,
                                               const float* __restrict__ lw,
                                               const float* __restrict__ lb,
                                               float* __restrict__ out) {
    const float* __restrict__ Tin = g_Ta;
    __shared__ float lws[HH * CC];
    __shared__ float hs[8][HH];
    __shared__ float lg[8][CC];
    int t = threadIdx.x, c = t & 63, g = t >> 6;
    int row = blockIdx.x * 8 + g;
    if (t < HH * CC) lws[t] = lw[t];
    if (c < HH) {
        const int*   cp = &g_cols[row * CAP];
        const float* vp = &g_vals[row * CAP];
        int cnt = g_cnt[row];
        float a0 = g_self[row] * Tin[row * HH + c], a1 = 0.f, a2 = 0.f, a3 = 0.f;
        int e = 0;
        for (; e + 4 <= cnt; e += 4) {
            int   c0 = cp[e], c1 = cp[e + 1], c2 = cp[e + 2], c3 = cp[e + 3];
            float w0 = vp[e], w1 = vp[e + 1], w2 = vp[e + 2], w3 = vp[e + 3];
            a0 += w0 * Tin[c0 * HH + c];
            a1 += w1 * Tin[c1 * HH + c];
            a2 += w2 * Tin[c2 * HH + c];
            a3 += w3 * Tin[c3 * HH + c];
        }
        for (; e < cnt; ++e) a0 += vp[e] * Tin[cp[e] * HH + c];
        hs[g][c] = ((a0 + a1) + (a2 + a3)) + b3[c];
    }
    __syncthreads();
    if (c < CC) {
        float o = lb[c];
        #pragma unroll
        for (int k = 0; k < HH; ++k)
            o += hs[g][k] * lws[k * CC + c];
        lg[g][c] = o;
    }
    __syncthreads();
    if (c < CC) {
        float m = fmaxf(fmaxf(lg[g][0], lg[g][1]), fmaxf(lg[g][2], lg[g][3]));
        float s = expf(lg[g][0] - m) + expf(lg[g][1] - m) +
                  expf(lg[g][2] - m) + expf(lg[g][3] - m);
        out[(size_t)row * CC + c] = lg[g][c] - m - logf(s);
    }
}

// ---------------------------------------------------------------------------
// Inputs resolved BY ELEMENT COUNT; same-size ties by relative order.
extern "C" void kernel_launch(void* const* d_in, const int* in_sizes, int n_in,
                              void* d_out, int out_size) {
    const float *x = 0, *adj = 0, *pvec = 0, *W1 = 0, *b1 = 0, *W2 = 0, *b2 = 0,
                *W3 = 0, *b3 = 0, *lin_w = 0, *lin_b = 0;
    int nb = 0, nw = 0;
    for (int i = 0; i < n_in; ++i) {
        const float* p = (const float*)d_in[i];
        switch (in_sizes[i]) {
            case NN * FF:            x = p;    break;
            case NN * NN:            adj = p;  break;
            case (NN * (NN + 1)) / 2: pvec = p; break;
            case FF * HH:            W1 = p;   break;
            case HH * HH:
                if (nw == 0) W2 = p; else W3 = p;
                ++nw; break;
            case HH:
                if (nb == 0) b1 = p; else if (nb == 1) b2 = p; else b3 = p;
                ++nb; break;
            case HH * CC:            lin_w = p; break;
            case CC:                 lin_b = p; break;
            default: break;
        }
    }
    float* out = (float*)d_out;

    k_build<<<NN / 8, 256>>>(adj, pvec);       // 1 warp/row
    k_xw<<<NN / 32, 512>>>(x, W1);             // g_Ta = x@W1 (+ dis finalize)
    k_norm<<<NN * 16 / 256, 256>>>();          // fold D^{-1/2} into edge weights
    k_layer<<<NN / 8, 512>>>(0, b1, W2);       // g_Ta -> g_Tb
    k_layer<<<NN / 8, 512>>>(1, b2, W3);       // g_Tb -> g_Ta
    k_final<<<NN / 8, 512>>>(b3, lin_w, lin_b, out);
}

// round 8
// speedup vs baseline: 1.2005x; 1.2005x over previous
#include <cuda_runtime.h>
#include <cuda_bf16.h>
#include <math.h>

#define NN   4096
#define FF   512
#define HH   60
#define CC   4
#define CAP  64      // max nnz per row of sub_adj (mean ~8.2)

// scratch (device globals; referenced ONLY from device code — see R3 post-mortem)
__device__ float g_deg[NN];          // zero at load; reset to 0 by k_xw each run
__device__ float g_dis[NN];
__device__ float g_self[NN];         // dis_i^2 (self-loop weight)
__device__ int   g_cnt[NN];
__device__ int   g_cols[NN * CAP];
__device__ float g_vals[NN * CAP];   // after k_norm: fully normalized edge weight
__device__ float g_Ta[NN * HH];
__device__ float g_Tb[NN * HH];

__device__ __forceinline__ void cp16(unsigned s, const void* g) {
    asm volatile("cp.async.cg.shared.global [%0], [%1], 16;\n" :: "r"(s), "l"(g));
}

// ---------------------------------------------------------------------------
// K1: scan sub_adj (67 MB, HBM floor ~9 us), warp-ballot edge compaction,
// gather P_vec at nonzeros, sigmoid, column-degree atomic accumulation.
__global__ void k_build(const float* __restrict__ adj, const float* __restrict__ pvec) {
    int warp = (blockIdx.x * blockDim.x + threadIdx.x) >> 5;
    int lane = threadIdx.x & 31;
    if (warp >= NN) return;
    const int row = warp;
    const float4* rp = reinterpret_cast<const float4*>(adj + (size_t)row * NN);
    int cnt = 0;
    #pragma unroll 4
    for (int it = 0; it < NN / 128; ++it) {
        float4 v = rp[it * 32 + lane];
        int jb = it * 128 + lane * 4;
        float vv[4] = {v.x, v.y, v.z, v.w};
        #pragma unroll
        for (int q = 0; q < 4; ++q) {
            bool nz = (vv[q] != 0.0f);
            unsigned m = __ballot_sync(0xffffffffu, nz);
            if (nz) {
                int j = jb + q;
                int slot = cnt + __popc(m & ((1u << lane) - 1u));
                int a = row > j ? row : j;
                int b = row > j ? j : row;
                float p = pvec[(size_t)a * (a + 1) / 2 + b];   // tril idx a(a+1)/2+b
                float s = vv[q] / (1.0f + expf(-p));            // sigmoid(p)*adj
                if (slot < CAP) {
                    g_cols[row * CAP + slot] = j;
                    g_vals[row * CAP + slot] = s;
                }
                atomicAdd(&g_deg[j], s);
            }
            cnt += __popc(m);
        }
    }
    if (lane == 0) g_cnt[row] = cnt < CAP ? cnt : CAP;
}

// ---------------------------------------------------------------------------
// K2: g_Ta = x @ W1 (4096x512 @ 512x60) — EXACT R4 config (measured ~11us):
// 128 blocks x 256 threads, 2 rows/thread, cp.async double-buffer, f32x2.
// Prologue finalizes g_dis and resets g_deg for graph replay.
__global__ void __launch_bounds__(256) k_xw(const float* __restrict__ x,
                                            const float* __restrict__ W) {
    int gid = blockIdx.x * 256 + threadIdx.x;
    if (gid < NN) {
        g_dis[gid] = rsqrtf(g_deg[gid] + 1.0f);  // +1: identity self-loop
        g_deg[gid] = 0.0f;
    }

    __shared__ __align__(16) float As[2][32][36];
    __shared__ __align__(16) float Ws[2][32][64];

    const int t  = threadIdx.x;
    const int tx = t & 15;
    const int ty = t >> 4;
    const int r0 = blockIdx.x * 32;

    { int b = t >> 7, rr = (t >> 2) & 31, cc = 60 + (t & 3); Ws[b][rr][cc] = 0.0f; }

    const int arow = t >> 3;
    const int akk  = (t & 7) * 4;
    const int wk   = t >> 3;
    const int wc   = (t & 7) * 8;

    auto issue = [&](int tile, int buf) {
        int k0 = tile * 32;
        unsigned sA = (unsigned)__cvta_generic_to_shared(&As[buf][arow][akk]);
        cp16(sA, x + (size_t)(r0 + arow) * FF + k0 + akk);
        unsigned sW = (unsigned)__cvta_generic_to_shared(&Ws[buf][wk][wc]);
        cp16(sW, W + (size_t)(k0 + wk) * HH + wc);
        if (wc + 4 < HH)
            cp16(sW + 16, W + (size_t)(k0 + wk) * HH + wc + 4);
        asm volatile("cp.async.commit_group;\n");
    };

    unsigned long long acc[2][2] = {{0ull, 0ull}, {0ull, 0ull}};

    issue(0, 0);
    int buf = 0;
    for (int tile = 0; tile < FF / 32; ++tile) {
        __syncthreads();
        if (tile < FF / 32 - 1) {
            issue(tile + 1, buf ^ 1);
            asm volatile("cp.async.wait_group 1;\n");
        } else {
            asm volatile("cp.async.wait_group 0;\n");
        }
        __syncthreads();
        #pragma unroll
        for (int k = 0; k < 32; ++k) {
            unsigned a0 = __float_as_uint(As[buf][2 * ty + 0][k]);
            unsigned a1 = __float_as_uint(As[buf][2 * ty + 1][k]);
            unsigned long long pa0, pa1;
            asm("mov.b64 %0, {%1, %1};" : "=l"(pa0) : "r"(a0));
            asm("mov.b64 %0, {%1, %1};" : "=l"(pa1) : "r"(a1));
            ulonglong2 w = *reinterpret_cast<const ulonglong2*>(&Ws[buf][k][4 * tx]);
            asm("fma.rn.f32x2 %0, %1, %2, %0;" : "+l"(acc[0][0]) : "l"(pa0), "l"(w.x));
            asm("fma.rn.f32x2 %0, %1, %2, %0;" : "+l"(acc[0][1]) : "l"(pa0), "l"(w.y));
            asm("fma.rn.f32x2 %0, %1, %2, %0;" : "+l"(acc[1][0]) : "l"(pa1), "l"(w.x));
            asm("fma.rn.f32x2 %0, %1, %2, %0;" : "+l"(acc[1][1]) : "l"(pa1), "l"(w.y));
        }
        buf ^= 1;
    }

    if (4 * tx < HH) {
        #pragma unroll
        for (int i = 0; i < 2; ++i) {
            unsigned lo0, hi0, lo1, hi1;
            asm("mov.b64 {%0, %1}, %2;" : "=r"(lo0), "=r"(hi0) : "l"(acc[i][0]));
            asm("mov.b64 {%0, %1}, %2;" : "=r"(lo1), "=r"(hi1) : "l"(acc[i][1]));
            float4 o = make_float4(__uint_as_float(lo0), __uint_as_float(hi0),
                                   __uint_as_float(lo1), __uint_as_float(hi1));
            int r = r0 + 2 * ty + i;
            *reinterpret_cast<float4*>(&g_Ta[(size_t)r * HH + 4 * tx]) = o;
        }
    }
}

// ---------------------------------------------------------------------------
// K3: fold D^{-1/2}: g_vals *= dis_i*dis_j; g_self = dis_i^2.
__global__ void k_norm() {
    int gid = blockIdx.x * 256 + threadIdx.x;
    int row = gid >> 4, le = gid & 15;
    if (row >= NN) return;
    float di = g_dis[row];
    int cnt = g_cnt[row];
    for (int e = le; e < cnt; e += 16)
        g_vals[row * CAP + e] *= di * g_dis[g_cols[row * CAP + e]];
    if (le == 0) g_self[row] = di * di;
}

// ---------------------------------------------------------------------------
// K4: WARP-PER-ROW fused layer: h = relu(SpMM + bias); Tout = h @ Wnext.
// Lane l owns cols {2l, 2l+1} (lanes 30,31 idle). Only __syncwarp between
// phases; one __syncthreads for the block-shared Ws stage.
__global__ void __launch_bounds__(256) k_layer(int src, const float* __restrict__ bias,
                                               const float* __restrict__ Wnext) {
    const float* __restrict__ Tin = src ? g_Tb : g_Ta;
    float* __restrict__ Tout      = src ? g_Ta : g_Tb;
    __shared__ float Ws[HH * HH];
    __shared__ float hs[8][HH];
    int t = threadIdx.x, w = t >> 5, l = t & 31;
    int row = blockIdx.x * 8 + w;
    for (int i = t; i < HH * HH; i += 256) Ws[i] = Wnext[i];
    __syncthreads();

    int c0 = 2 * l;
    if (c0 < HH) {
        const int*   cp = &g_cols[row * CAP];
        const float* vp = &g_vals[row * CAP];
        int cnt = g_cnt[row];
        float2 sv = *reinterpret_cast<const float2*>(&Tin[row * HH + c0]);
        float sw = g_self[row];
        float a00 = sw * sv.x, a01 = sw * sv.y;
        float a10 = 0.f, a11 = 0.f, a20 = 0.f, a21 = 0.f, a30 = 0.f, a31 = 0.f;
        int e = 0;
        for (; e + 4 <= cnt; e += 4) {
            int4   cc = *reinterpret_cast<const int4*>(&cp[e]);
            float4 ww = *reinterpret_cast<const float4*>(&vp[e]);
            float2 t0 = *reinterpret_cast<const float2*>(&Tin[cc.x * HH + c0]);
            float2 t1 = *reinterpret_cast<const float2*>(&Tin[cc.y * HH + c0]);
            float2 t2 = *reinterpret_cast<const float2*>(&Tin[cc.z * HH + c0]);
            float2 t3 = *reinterpret_cast<const float2*>(&Tin[cc.w * HH + c0]);
            a00 += ww.x * t0.x; a01 += ww.x * t0.y;
            a10 += ww.y * t1.x; a11 += ww.y * t1.y;
            a20 += ww.z * t2.x; a21 += ww.z * t2.y;
            a30 += ww.w * t3.x; a31 += ww.w * t3.y;
        }
        for (; e < cnt; ++e) {
            float2 tv = *reinterpret_cast<const float2*>(&Tin[cp[e] * HH + c0]);
            a00 += vp[e] * tv.x; a01 += vp[e] * tv.y;
        }
        float2 bb = *reinterpret_cast<const float2*>(&bias[c0]);
        hs[w][c0]     = fmaxf((a00 + a10) + (a20 + a30) + bb.x, 0.0f);
        hs[w][c0 + 1] = fmaxf((a01 + a11) + (a21 + a31) + bb.y, 0.0f);
    }
    __syncwarp();
    if (c0 < HH) {
        float o00 = 0.f, o01 = 0.f, o10 = 0.f, o11 = 0.f;
        #pragma unroll
        for (int k = 0; k < HH; k += 2) {
            float hk0 = hs[w][k], hk1 = hs[w][k + 1];
            float2 w0 = *reinterpret_cast<const float2*>(&Ws[k * HH + c0]);
            float2 w1 = *reinterpret_cast<const float2*>(&Ws[(k + 1) * HH + c0]);
            o00 += hk0 * w0.x; o01 += hk0 * w0.y;
            o10 += hk1 * w1.x; o11 += hk1 * w1.y;
        }
        *reinterpret_cast<float2*>(&Tout[row * HH + c0]) =
            make_float2(o00 + o10, o01 + o11);
    }
}

// ---------------------------------------------------------------------------
// K5: WARP-PER-ROW final: H3 = SpMM(g_Ta)+b3; logits via per-lane partials +
// butterfly reduce (register-only); log_softmax; lane 0 writes float4.
__global__ void __launch_bounds__(256) k_final(const float* __restrict__ b3,
                                               const float* __restrict__ lw,
                                               const float* __restrict__ lb,
                                               float* __restrict__ out) {
    const float* __restrict__ Tin = g_Ta;
    int t = threadIdx.x, w = t >> 5, l = t & 31;
    int row = blockIdx.x * 8 + w;
    int c0 = 2 * l;
    float p0 = 0.f, p1 = 0.f, p2 = 0.f, p3 = 0.f;
    if (c0 < HH) {
        const int*   cp = &g_cols[row * CAP];
        const float* vp = &g_vals[row * CAP];
        int cnt = g_cnt[row];
        float2 sv = *reinterpret_cast<const float2*>(&Tin[row * HH + c0]);
        float sw = g_self[row];
        float a00 = sw * sv.x, a01 = sw * sv.y;
        float a10 = 0.f, a11 = 0.f, a20 = 0.f, a21 = 0.f, a30 = 0.f, a31 = 0.f;
        int e = 0;
        for (; e + 4 <= cnt; e += 4) {
            int4   cc = *reinterpret_cast<const int4*>(&cp[e]);
            float4 ww = *reinterpret_cast<const float4*>(&vp[e]);
            float2 t0 = *reinterpret_cast<const float2*>(&Tin[cc.x * HH + c0]);
            float2 t1 = *reinterpret_cast<const float2*>(&Tin[cc.y * HH + c0]);
            float2 t2 = *reinterpret_cast<const float2*>(&Tin[cc.z * HH + c0]);
            float2 t3 = *reinterpret_cast<const float2*>(&Tin[cc.w * HH + c0]);
            a00 += ww.x * t0.x; a01 += ww.x * t0.y;
            a10 += ww.y * t1.x; a11 += ww.y * t1.y;
            a20 += ww.z * t2.x; a21 += ww.z * t2.y;
            a30 += ww.w * t3.x; a31 += ww.w * t3.y;
        }
        for (; e < cnt; ++e) {
            float2 tv = *reinterpret_cast<const float2*>(&Tin[cp[e] * HH + c0]);
            a00 += vp[e] * tv.x; a01 += vp[e] * tv.y;
        }
        float2 bb = *reinterpret_cast<const float2*>(&b3[c0]);
        float h0 = (a00 + a10) + (a20 + a30) + bb.x;
        float h1 = (a01 + a11) + (a21 + a31) + bb.y;
        float4 l0 = *reinterpret_cast<const float4*>(&lw[c0 * CC]);       // 16B aligned
        float4 l1 = *reinterpret_cast<const float4*>(&lw[(c0 + 1) * CC]);
        p0 = h0 * l0.x + h1 * l1.x;
        p1 = h0 * l0.y + h1 * l1.y;
        p2 = h0 * l0.z + h1 * l1.z;
        p3 = h0 * l0.w + h1 * l1.w;
    }
    #pragma unroll
    for (int off = 16; off; off >>= 1) {
        p0 += __shfl_xor_sync(0xffffffffu, p0, off);
        p1 += __shfl_xor_sync(0xffffffffu, p1, off);
        p2 += __shfl_xor_sync(0xffffffffu, p2, off);
        p3 += __shfl_xor_sync(0xffffffffu, p3, off);
    }
    if (l == 0) {
        float lg0 = p0 + lb[0], lg1 = p1 + lb[1], lg2 = p2 + lb[2], lg3 = p3 + lb[3];
        float m = fmaxf(fmaxf(lg0, lg1), fmaxf(lg2, lg3));
        float s = expf(lg0 - m) + expf(lg1 - m) + expf(lg2 - m) + expf(lg3 - m);
        float ls = m + logf(s);
        *reinterpret_cast<float4*>(&out[(size_t)row * CC]) =
            make_float4(lg0 - ls, lg1 - ls, lg2 - ls, lg3 - ls);
    }
}

// ---------------------------------------------------------------------------
// Inputs resolved BY ELEMENT COUNT; same-size ties by relative order.
extern "C" void kernel_launch(void* const* d_in, const int* in_sizes, int n_in,
                              void* d_out, int out_size) {
    const float *x = 0, *adj = 0, *pvec = 0, *W1 = 0, *b1 = 0, *W2 = 0, *b2 = 0,
                *W3 = 0, *b3 = 0, *lin_w = 0, *lin_b = 0;
    int nb = 0, nw = 0;
    for (int i = 0; i < n_in; ++i) {
        const float* p = (const float*)d_in[i];
        switch (in_sizes[i]) {
            case NN * FF:            x = p;    break;
            case NN * NN:            adj = p;  break;
            case (NN * (NN + 1)) / 2: pvec = p; break;
            case FF * HH:            W1 = p;   break;
            case HH * HH:
                if (nw == 0) W2 = p; else W3 = p;
                ++nw; break;
            case HH:
                if (nb == 0) b1 = p; else if (nb == 1) b2 = p; else b3 = p;
                ++nb; break;
            case HH * CC:            lin_w = p; break;
            case CC:                 lin_b = p; break;
            default: break;
        }
    }
    float* out = (float*)d_out;

    k_build<<<NN / 8, 256>>>(adj, pvec);       // 1 warp/row
    k_xw<<<NN / 32, 256>>>(x, W1);             // g_Ta = x@W1 (+ dis finalize)
    k_norm<<<NN * 16 / 256, 256>>>();          // fold D^{-1/2} into edges
    k_layer<<<NN / 8, 256>>>(0, b1, W2);       // g_Ta -> g_Tb
    k_layer<<<NN / 8, 256>>>(1, b2, W3);       // g_Tb -> g_Ta
    k_final<<<NN / 8, 256>>>(b3, lin_w, lin_b, out);
}